// round 11
// baseline (speedup 1.0000x reference)
#include <cuda_runtime.h>
#include <cuda_bf16.h>
#include <cuda_fp16.h>
#include <math.h>

#define BSZ 4096
#define DDIM 128
#define KCODES 2048
#define SSTG 4
#define LHTOT 1280

// -------- device scratch (static; no allocation) --------
__device__ float g_zq[BSZ * DDIM];
__device__ float g_bet[BSZ * LHTOT];
__device__ float g_e2[SSTG * KCODES];
__device__ float g_lpart[256];
__device__ __half g_W0f[256 * 64];
__device__ __half g_Whf[4 * 256 * 256];

typedef unsigned long long ull;

// -------- generic helpers --------
__device__ __forceinline__ float dot4(float4 a, float4 b) {
    return fmaf(a.x, b.x, fmaf(a.y, b.y, fmaf(a.z, b.z, a.w * b.w)));
}
__device__ __forceinline__ float4 f4add(float4 a, float4 b) {
    return make_float4(a.x + b.x, a.y + b.y, a.z + b.z, a.w + b.w);
}
__device__ __forceinline__ float4 f4sub(float4 a, float4 b) {
    return make_float4(a.x - b.x, a.y - b.y, a.z - b.z, a.w - b.w);
}
__device__ __forceinline__ unsigned smem_u32(const void* p) {
    unsigned a;
    asm("{ .reg .u64 t; cvta.to.shared.u64 t, %1; cvt.u32.u64 %0, t; }" : "=r"(a) : "l"(p));
    return a;
}
__device__ __forceinline__ void sts32(unsigned a, unsigned v) {
    asm volatile("st.shared.u32 [%0], %1;" :: "r"(a), "r"(v));
}
__device__ __forceinline__ void sts16(unsigned a, unsigned short v) {
    asm volatile("st.shared.u16 [%0], %1;" :: "r"(a), "h"(v));
}
__device__ __forceinline__ unsigned lds32(unsigned a) {
    unsigned v; asm volatile("ld.shared.b32 %0, [%1];" : "=r"(v) : "r"(a)); return v;
}
__device__ __forceinline__ void ldm4(unsigned* r, unsigned a) {
    asm volatile("ldmatrix.sync.aligned.m8n8.x4.shared.b16 {%0,%1,%2,%3}, [%4];"
        : "=r"(r[0]), "=r"(r[1]), "=r"(r[2]), "=r"(r[3]) : "r"(a));
}
// fp16 mma m16n8k16 -> f32 accum (baseline sm_80)
__device__ __forceinline__ void mma_f16h(float* c, const unsigned* a, unsigned b0, unsigned b1) {
    asm volatile("mma.sync.aligned.m16n8k16.row.col.f32.f16.f16.f32 "
        "{%0,%1,%2,%3},{%4,%5,%6,%7},{%8,%9},{%0,%1,%2,%3};"
        : "+f"(c[0]), "+f"(c[1]), "+f"(c[2]), "+f"(c[3])
        : "r"(a[0]), "r"(a[1]), "r"(a[2]), "r"(a[3]), "r"(b0), "r"(b1));
}
__device__ __forceinline__ void cpa16(unsigned dst, const void* src) {
    asm volatile("cp.async.cg.shared.global [%0], [%1], 16;" :: "r"(dst), "l"(src));
}
#define CPA_COMMIT() asm volatile("cp.async.commit_group;" ::: "memory")
#define CPA_WAIT0()  asm volatile("cp.async.wait_group 0;" ::: "memory")

// accurate fp32 sincos (Cody-Waite; |a| <= 2^9*pi)
__device__ __forceinline__ void sc_f32(float a, float& s, float& c) {
    float n = rintf(a * 0.31830988618f);
    float r = fmaf(-n, 3.140625f, a);
    r = fmaf(-n, 9.67502593994140625e-4f, r);
    r = fmaf(-n, 1.50995788e-7f, r);
    float r2 = r * r;
    float sp = fmaf(r2, fmaf(r2, fmaf(r2, fmaf(r2, fmaf(r2, -2.5052108e-8f, 2.7557319e-6f),
               -1.9841270e-4f), 8.3333333e-3f), -1.6666667e-1f), 1.f);
    float cp = fmaf(r2, fmaf(r2, fmaf(r2, fmaf(r2, fmaf(r2, -2.7557319e-7f, 2.4801587e-5f),
               -1.3888889e-3f), 4.1666667e-2f), -0.5f), 1.f);
    s = r * sp; c = cp;
    if (((int)n) & 1) { s = -s; c = -c; }
}

// ======================================================================
// kernel 1: ||e||^2
// ======================================================================
__global__ void k_e2(const float* __restrict__ emb) {
    int c = blockIdx.x * 256 + threadIdx.x;
    const float4* row = (const float4*)(emb + (size_t)c * DDIM);
    float s = 0.f;
#pragma unroll 8
    for (int i = 0; i < 32; ++i) {
        float4 v = row[i];
        s += v.x * v.x + v.y * v.y + v.z * v.z + v.w * v.w;
    }
    g_e2[c] = s;
}

// ======================================================================
// kernel 2: residual VQ (validated; at FFMA roofline)
// ======================================================================
__global__ __launch_bounds__(256) void k_vq(
    const int* __restrict__ li, const float* __restrict__ lat,
    const float* __restrict__ emb)
{
    __shared__ float4 zc4[16 * 32];
    __shared__ float4 em4[64 * 33];
    __shared__ float  e2s[64];
    __shared__ int    win[16];
    __shared__ float  lred[8];

    const int t = threadIdx.x, bp = t >> 5, cl = t & 31;
    const int b0 = 2 * bp, b1 = b0 + 1;
    const int B0 = blockIdx.x * 16;
    const int l0 = li[B0 + b0], l1 = li[B0 + b1];

    float4 r0 = make_float4(0, 0, 0, 0), r1 = r0, q0 = r0, q1 = r0;
    float loss = 0.f;

    for (int s = 0; s < SSTG; ++s) {
        float4 z0 = *(const float4*)&lat[((size_t)l0 * SSTG + s) * DDIM + cl * 4];
        float4 z1 = *(const float4*)&lat[((size_t)l1 * SSTG + s) * DDIM + cl * 4];
        r0 = f4add(r0, z0); r1 = f4add(r1, z1);
        float4 ca = f4sub(r0, q0), cb = f4sub(r1, q1);
        zc4[b0 * 32 + cl] = ca;
        zc4[b1 * 32 + cl] = cb;

        float bd0 = 3.4e38f, bd1 = 3.4e38f;
        int bi0 = 0, bi1 = 0;

        for (int tb = 0; tb < KCODES; tb += 64) {
            __syncthreads();
#pragma unroll
            for (int i = 0; i < 8; ++i) {
                int lin = t + 256 * i;
                int c = lin >> 5, k4 = lin & 31;
                em4[c * 33 + k4] =
                    *(const float4*)&emb[((size_t)s * KCODES + tb + c) * DDIM + k4 * 4];
            }
            if (t < 64) e2s[t] = g_e2[s * KCODES + tb + t];
            __syncthreads();

            float a00 = 0, a01 = 0, a10 = 0, a11 = 0;
#pragma unroll 4
            for (int k4 = 0; k4 < 32; ++k4) {
                float4 za = zc4[b0 * 32 + k4];
                float4 zb = zc4[b1 * 32 + k4];
                float4 e0 = em4[cl * 33 + k4];
                float4 e1 = em4[(cl + 32) * 33 + k4];
                a00 += dot4(e0, za); a01 += dot4(e0, zb);
                a10 += dot4(e1, za); a11 += dot4(e1, zb);
            }
            float d;
            d = fmaf(-2.f, a00, e2s[cl]);      if (d < bd0) { bd0 = d; bi0 = tb + cl; }
            d = fmaf(-2.f, a10, e2s[cl + 32]); if (d < bd0) { bd0 = d; bi0 = tb + cl + 32; }
            d = fmaf(-2.f, a01, e2s[cl]);      if (d < bd1) { bd1 = d; bi1 = tb + cl; }
            d = fmaf(-2.f, a11, e2s[cl + 32]); if (d < bd1) { bd1 = d; bi1 = tb + cl + 32; }
        }
#pragma unroll
        for (int off = 16; off; off >>= 1) {
            float od = __shfl_down_sync(~0u, bd0, off);
            int   oi = __shfl_down_sync(~0u, bi0, off);
            if (od < bd0 || (od == bd0 && oi < bi0)) { bd0 = od; bi0 = oi; }
            od = __shfl_down_sync(~0u, bd1, off);
            oi = __shfl_down_sync(~0u, bi1, off);
            if (od < bd1 || (od == bd1 && oi < bi1)) { bd1 = od; bi1 = oi; }
        }
        if (cl == 0) { win[b0] = bi0; win[b1] = bi1; }
        __syncthreads();
        int w0 = win[b0], w1 = win[b1];
        float4 e0 = *(const float4*)&emb[((size_t)s * KCODES + w0) * DDIM + cl * 4];
        float4 e1 = *(const float4*)&emb[((size_t)s * KCODES + w1) * DDIM + cl * 4];
        float4 d0 = f4sub(e0, ca), d1 = f4sub(e1, cb);
        loss += dot4(d0, d0) + dot4(d1, d1);
        q0 = f4add(q0, e0); q1 = f4add(q1, e1);
    }
    *(float4*)&g_zq[(size_t)(B0 + b0) * DDIM + cl * 4] = q0;
    *(float4*)&g_zq[(size_t)(B0 + b1) * DDIM + cl * 4] = q1;

#pragma unroll
    for (int off = 16; off; off >>= 1) loss += __shfl_down_sync(~0u, loss, off);
    if (cl == 0) lred[bp] = loss;
    __syncthreads();
    if (t == 0) {
        float s = 0.f;
        for (int i = 0; i < 8; ++i) s += lred[i];
        g_lpart[blockIdx.x] = s;
    }
}

// ======================================================================
// kernel 3: betas (validated)
// ======================================================================
__global__ __launch_bounds__(256) void k_betas(
    const float* __restrict__ mW, const float* __restrict__ mb)
{
    extern __shared__ float sm[];
    float* Zs = sm;
    float* Ws = sm + 64 * 129;
    const int t = threadIdx.x;
    const int i0 = blockIdx.x * 64, r0 = blockIdx.y * 64;
    for (int lin = t; lin < 8192; lin += 256) {
        int r = lin >> 7, k = lin & 127;
        Zs[r * 129 + k] = g_zq[(size_t)(i0 + r) * DDIM + k];
        Ws[r * 129 + k] = mW[(size_t)(r0 + r) * DDIM + k];
    }
    __syncthreads();
    const int ix = t & 15, wy = t >> 4;
    float acc[4][4] = {};
    for (int k = 0; k < 128; ++k) {
        float z[4], w[4];
#pragma unroll
        for (int m = 0; m < 4; ++m) {
            z[m] = Zs[(ix + 16 * m) * 129 + k];
            w[m] = Ws[(wy + 16 * m) * 129 + k];
        }
#pragma unroll
        for (int m = 0; m < 4; ++m)
#pragma unroll
            for (int n = 0; n < 4; ++n) acc[m][n] = fmaf(z[m], w[n], acc[m][n]);
    }
#pragma unroll
    for (int n = 0; n < 4; ++n) {
        float bias = mb[r0 + wy + 16 * n];
#pragma unroll
        for (int m = 0; m < 4; ++m)
            g_bet[(size_t)(i0 + ix + 16 * m) * LHTOT + r0 + wy + 16 * n] = acc[m][n] + bias;
    }
}

// ======================================================================
// kernel 4: fp16 weight conversion (W0 padded 42->64)
// ======================================================================
__global__ void k_wprep(const float* __restrict__ W0, const float* __restrict__ Wh) {
    int i = blockIdx.x * 256 + threadIdx.x;   // grid covers 262144
    if (i < 256 * 64) {
        int n = i >> 6, k = i & 63;
        float w = (k < 42) ? W0[n * 42 + k] : 0.f;
        g_W0f[i] = __float2half_rn(w);
    }
    g_Whf[i] = __float2half_rn(Wh[i]);
}

// ======================================================================
// kernel 5: fp16 HMMA fused MLP — 4 images/CTA (M=256), 512 threads
//   16 warps: wm = wid&3 (m 64-quarter), wn = wid>>2 (n 64-quarter),
//   warp tile 64x64 (128 acc regs). X plane fp16 [256][264] (stride 528 B).
//   W stages: 2 x [256 rows][72 halves] (stride 144 B). 17 K=64 panels.
// ======================================================================
__global__ __launch_bounds__(512, 1) void k_mlp16(
    const float* __restrict__ coords, const float* __restrict__ b0v,
    const float* __restrict__ bhv, const float* __restrict__ lW,
    const float* __restrict__ lb, float* __restrict__ out)
{
    extern __shared__ char dyn[];
    __shared__ float bbs[1024];
    __shared__ float lWs[768];

    const unsigned XB = smem_u32(dyn);
    const unsigned WB = XB + 135168u;

    const int t = threadIdx.x, wid = t >> 5, l = t & 31;
    const int wm = wid & 3, wn = wid >> 2;
    const int blk = blockIdx.x;

    const unsigned aoffb = (unsigned)(wm * 64 + (l & 15)) * 528u + (unsigned)((l >> 4) << 3) * 2u;
    const unsigned boffb = (unsigned)(wn * 64 + ((l >> 4) << 3) + (l & 7)) * 144u
                         + (unsigned)(((l >> 3) & 1) << 4);

    auto issue = [&](int g) {
        const __half* Wg; int rstride, k0;
        if (g == 0) { Wg = g_W0f; rstride = 64; k0 = 0; }
        else {
            int Lw = (g - 1) >> 2;
            Wg = g_Whf + (size_t)Lw * 65536; rstride = 256; k0 = ((g - 1) & 3) * 64;
        }
        int row = t >> 1, half = t & 1;
        const __half* src = Wg + (size_t)row * rstride + k0 + half * 32;
        unsigned dst = WB + (unsigned)(g & 1) * 36864u + (unsigned)row * 144u + (unsigned)half * 64u;
#pragma unroll
        for (int c = 0; c < 4; ++c) cpa16(dst + (unsigned)c * 16u, src + c * 8);
        CPA_COMMIT();
    };

    issue(0);

    // ---- prefetch ALL bias+beta into registers ----
    const int nidx = t & 255, ih = t >> 8;   // ih in {0,1}; covers images 2*ih, 2*ih+1
    float bbr[5][2];
#pragma unroll
    for (int L = 0; L < 5; ++L) {
        float bias = (L == 0) ? b0v[nidx] : bhv[(L - 1) * 256 + nidx];
        bbr[L][0] = bias + g_bet[(size_t)(blk * 4 + 2 * ih) * LHTOT + L * 256 + nidx];
        bbr[L][1] = bias + g_bet[(size_t)(blk * 4 + 2 * ih + 1) * LHTOT + L * 256 + nidx];
    }
    for (int i = t; i < 768; i += 512) lWs[i] = lW[i];

    // ---- positional encoding -> X rows 0..255 (fp16), cols 42..63 zero ----
    if (t < 256) {
        const float* cp = coords + ((size_t)(blk * 4) * 64 + t) * 2;
        float cx = cp[0], cy = cp[1];
        unsigned rowo = XB + (unsigned)t * 528u;
        auto wrf = [&](int k, float v) {
            __half h = __float2half_rn(v);
            sts16(rowo + 2u * (unsigned)k, *(unsigned short*)&h);
        };
        wrf(0, cx); wrf(1, cy);
        float fr = 3.14159274101257324f;
#pragma unroll
        for (int f = 0; f < 10; ++f) {
            float sx, cxv, sy, cyv;
            sc_f32(cx * fr, sx, cxv);
            sc_f32(cy * fr, sy, cyv);
            wrf(2 + f, sx); wrf(12 + f, sy);
            wrf(22 + f, cxv); wrf(32 + f, cyv);
            fr *= 2.f;
        }
#pragma unroll
        for (int k = 42; k < 64; ++k) wrf(k, 0.f);
    }

    float acc[4][8][4];
#pragma unroll
    for (int mt = 0; mt < 4; ++mt)
#pragma unroll
        for (int nc = 0; nc < 8; ++nc)
#pragma unroll
            for (int q = 0; q < 4; ++q) acc[mt][nc][q] = 0.f;

    int L = 0;
#pragma unroll 1
    for (int g = 0; g < 17; ++g) {
        CPA_WAIT0();        // panel g resident
        __syncthreads();    // publishes panel g + X writes; guards stage reuse
        if (g + 1 < 17) issue(g + 1);   // overlaps mma(g)

        const unsigned wb = WB + (unsigned)(g & 1) * 36864u;
        const int kb = (g == 0) ? 0 : ((g - 1) & 3) * 64;
#pragma unroll 2
        for (int ks = 0; ks < 4; ++ks) {
            unsigned xc = (unsigned)(kb + ks * 16) * 2u;
            unsigned a[4][4];
#pragma unroll
            for (int mt = 0; mt < 4; ++mt)
                ldm4(a[mt], XB + aoffb + xc + (unsigned)mt * (16u * 528u));
#pragma unroll
            for (int bg = 0; bg < 4; ++bg) {
                unsigned bf[4];
                ldm4(bf, wb + boffb + (unsigned)bg * (16u * 144u) + (unsigned)(ks * 32));
#pragma unroll
                for (int mt = 0; mt < 4; ++mt) {
                    mma_f16h(acc[mt][2 * bg],     a[mt], bf[0], bf[1]);
                    mma_f16h(acc[mt][2 * bg + 1], a[mt], bf[2], bf[3]);
                }
            }
        }

        const bool layerEnd = (g == 0) || ((g - 1) & 3) == 3;
        if (layerEnd) {
            __syncthreads();          // all warps done reading X this layer
            bbs[(2 * ih) * 256 + nidx]     = bbr[L][0];
            bbs[(2 * ih + 1) * 256 + nidx] = bbr[L][1];
            __syncthreads();
            const float* bb = bbs + wm * 256;   // image index = wm (64 rows/img)
#pragma unroll
            for (int mt = 0; mt < 4; ++mt) {
                unsigned ro0 = XB + (unsigned)(wm * 64 + mt * 16 + (l >> 2)) * 528u;
                unsigned ro1 = ro0 + 8u * 528u;
#pragma unroll
                for (int nc = 0; nc < 8; ++nc) {
                    int cb = wn * 64 + nc * 8 + (l & 3) * 2;
                    float b0f = bb[cb], b1f = bb[cb + 1];
                    float x0 = fmaxf(acc[mt][nc][0] + b0f, 0.f);
                    float x1 = fmaxf(acc[mt][nc][1] + b1f, 0.f);
                    float y0 = fmaxf(acc[mt][nc][2] + b0f, 0.f);
                    float y1 = fmaxf(acc[mt][nc][3] + b1f, 0.f);
                    __half2 h0 = __floats2half2_rn(x0, x1);
                    __half2 h1 = __floats2half2_rn(y0, y1);
                    sts32(ro0 + (unsigned)cb * 2u, *(unsigned*)&h0);
                    sts32(ro1 + (unsigned)cb * 2u, *(unsigned*)&h1);
                    acc[mt][nc][0] = 0.f; acc[mt][nc][1] = 0.f;
                    acc[mt][nc][2] = 0.f; acc[mt][nc][3] = 0.f;
                }
            }
            ++L;
            // next panel's top __syncthreads publishes the new X
        }
    }
    __syncthreads();   // final X visible

    // ---- final linear layer: V=3, fp32 from fp16 plane ----
    if (t < 256) {
        float a0 = 0.f, a1 = 0.f, a2 = 0.f;
        unsigned xr = XB + (unsigned)t * 528u;
#pragma unroll 8
        for (int k2 = 0; k2 < 128; ++k2) {
            unsigned hv = lds32(xr + k2 * 4u);
            __half2 h = *(__half2*)&hv;
            float x0 = __half2float(h.x), x1 = __half2float(h.y);
            int k = 2 * k2;
            a0 = fmaf(x0, lWs[k], fmaf(x1, lWs[k + 1], a0));
            a1 = fmaf(x0, lWs[256 + k], fmaf(x1, lWs[256 + k + 1], a1));
            a2 = fmaf(x0, lWs[512 + k], fmaf(x1, lWs[512 + k + 1], a2));
        }
        size_t ob = ((size_t)blk * 256 + t) * 3;
        out[ob]     = a0 + lb[0];
        out[ob + 1] = a1 + lb[1];
        out[ob + 2] = a2 + lb[2];
    }
}

// ======================================================================
// kernel 6: deterministic loss finalize
// ======================================================================
__global__ void k_loss(float* out, int has) {
    if (!has) return;
    float s = 0.f;
    for (int i = 0; i < 256; ++i) s += g_lpart[i];
    out[786432] = s * (0.25f / (4096.f * 128.f));
}

extern "C" void kernel_launch(void* const* d_in, const int* in_sizes, int n_in,
                              void* d_out, int out_size) {
    const float* coords = (const float*)d_in[0];
    const int*   li     = (const int*)d_in[1];
    const float* lat    = (const float*)d_in[2];
    const float* emb    = (const float*)d_in[3];
    const float* mW     = (const float*)d_in[4];
    const float* mb     = (const float*)d_in[5];
    const float* W0     = (const float*)d_in[6];
    const float* b0v    = (const float*)d_in[7];
    const float* Wh     = (const float*)d_in[8];
    const float* bh     = (const float*)d_in[9];
    const float* lW     = (const float*)d_in[10];
    const float* lb     = (const float*)d_in[11];
    float* out = (float*)d_out;

    const int MLP_SMEM = 208896;   // X fp16 256x528B (135168) + 2 W stages (2*36864)
    cudaFuncSetAttribute(k_mlp16, cudaFuncAttributeMaxDynamicSharedMemorySize, MLP_SMEM);
    cudaFuncSetAttribute(k_betas, cudaFuncAttributeMaxDynamicSharedMemorySize, 66048);

    k_wprep<<<1024, 256>>>(W0, Wh);
    k_e2<<<32, 256>>>(emb);
    k_vq<<<256, 256>>>(li, lat, emb);
    k_betas<<<dim3(64, 20), 256, 66048>>>(mW, mb);
    k_mlp16<<<1024, 512, MLP_SMEM>>>(coords, b0v, bh, lW, lb, out);
    k_loss<<<1, 1>>>(out, out_size > 786432 ? 1 : 0);
}

// round 12
// speedup vs baseline: 1.4376x; 1.4376x over previous
#include <cuda_runtime.h>
#include <cuda_bf16.h>
#include <cuda_fp16.h>
#include <math.h>

#define BSZ 4096
#define DDIM 128
#define KCODES 2048
#define SSTG 4
#define LHTOT 1280

// -------- device scratch (static; no allocation) --------
__device__ float g_zq[BSZ * DDIM];
__device__ float g_bet[BSZ * LHTOT];
__device__ float g_e2[SSTG * KCODES];
__device__ float g_lpart[256];
__device__ __half g_W0f[256 * 64];
__device__ __half g_Whf[4 * 256 * 256];

typedef unsigned long long ull;

// -------- generic helpers --------
__device__ __forceinline__ float dot4(float4 a, float4 b) {
    return fmaf(a.x, b.x, fmaf(a.y, b.y, fmaf(a.z, b.z, a.w * b.w)));
}
__device__ __forceinline__ float4 f4add(float4 a, float4 b) {
    return make_float4(a.x + b.x, a.y + b.y, a.z + b.z, a.w + b.w);
}
__device__ __forceinline__ float4 f4sub(float4 a, float4 b) {
    return make_float4(a.x - b.x, a.y - b.y, a.z - b.z, a.w - b.w);
}
__device__ __forceinline__ unsigned smem_u32(const void* p) {
    unsigned a;
    asm("{ .reg .u64 t; cvta.to.shared.u64 t, %1; cvt.u32.u64 %0, t; }" : "=r"(a) : "l"(p));
    return a;
}
__device__ __forceinline__ void sts32(unsigned a, unsigned v) {
    asm volatile("st.shared.u32 [%0], %1;" :: "r"(a), "r"(v));
}
__device__ __forceinline__ void sts16(unsigned a, unsigned short v) {
    asm volatile("st.shared.u16 [%0], %1;" :: "r"(a), "h"(v));
}
__device__ __forceinline__ unsigned lds32(unsigned a) {
    unsigned v; asm volatile("ld.shared.b32 %0, [%1];" : "=r"(v) : "r"(a)); return v;
}
__device__ __forceinline__ void ldm4(unsigned* r, unsigned a) {
    asm volatile("ldmatrix.sync.aligned.m8n8.x4.shared.b16 {%0,%1,%2,%3}, [%4];"
        : "=r"(r[0]), "=r"(r[1]), "=r"(r[2]), "=r"(r[3]) : "r"(a));
}
// fp16 mma m16n8k16 -> f32 accum (baseline sm_80)
__device__ __forceinline__ void mma_f16h(float* c, const unsigned* a, unsigned b0, unsigned b1) {
    asm volatile("mma.sync.aligned.m16n8k16.row.col.f32.f16.f16.f32 "
        "{%0,%1,%2,%3},{%4,%5,%6,%7},{%8,%9},{%0,%1,%2,%3};"
        : "+f"(c[0]), "+f"(c[1]), "+f"(c[2]), "+f"(c[3])
        : "r"(a[0]), "r"(a[1]), "r"(a[2]), "r"(a[3]), "r"(b0), "r"(b1));
}
__device__ __forceinline__ void cpa16(unsigned dst, const void* src) {
    asm volatile("cp.async.cg.shared.global [%0], [%1], 16;" :: "r"(dst), "l"(src));
}
#define CPA_COMMIT() asm volatile("cp.async.commit_group;" ::: "memory")
#define CPA_WAIT0()  asm volatile("cp.async.wait_group 0;" ::: "memory")

// packed fp32x2 (validated on this harness in R4)
__device__ __forceinline__ ull pk2(float x, float y) {
    ull r; asm("mov.b64 %0,{%1,%2};" : "=l"(r) : "f"(x), "f"(y)); return r;
}
__device__ __forceinline__ void upk2(ull v, float& x, float& y) {
    asm("mov.b64 {%0,%1},%2;" : "=f"(x), "=f"(y) : "l"(v));
}
__device__ __forceinline__ void fma2(ull& d, ull a, ull b) {
    asm("fma.rn.f32x2 %0,%1,%2,%0;" : "+l"(d) : "l"(a), "l"(b));
}

// accurate fp32 sincos (Cody-Waite; |a| <= 2^9*pi)
__device__ __forceinline__ void sc_f32(float a, float& s, float& c) {
    float n = rintf(a * 0.31830988618f);
    float r = fmaf(-n, 3.140625f, a);
    r = fmaf(-n, 9.67502593994140625e-4f, r);
    r = fmaf(-n, 1.50995788e-7f, r);
    float r2 = r * r;
    float sp = fmaf(r2, fmaf(r2, fmaf(r2, fmaf(r2, fmaf(r2, -2.5052108e-8f, 2.7557319e-6f),
               -1.9841270e-4f), 8.3333333e-3f), -1.6666667e-1f), 1.f);
    float cp = fmaf(r2, fmaf(r2, fmaf(r2, fmaf(r2, fmaf(r2, -2.7557319e-7f, 2.4801587e-5f),
               -1.3888889e-3f), 4.1666667e-2f), -0.5f), 1.f);
    s = r * sp; c = cp;
    if (((int)n) & 1) { s = -s; c = -c; }
}

// ======================================================================
// kernel 1: fused prep — fp16 weight conversion + ||e||^2
// ======================================================================
__global__ void k_prep(const float* __restrict__ W0, const float* __restrict__ Wh,
                       const float* __restrict__ emb) {
    int i = blockIdx.x * 256 + threadIdx.x;   // 0 .. 262143
    if (i < 256 * 64) {
        int n = i >> 6, k = i & 63;
        float w = (k < 42) ? W0[n * 42 + k] : 0.f;
        g_W0f[i] = __float2half_rn(w);
    }
    g_Whf[i] = __float2half_rn(Wh[i]);
    if (i < SSTG * KCODES) {
        const float4* row = (const float4*)(emb + (size_t)i * DDIM);
        float s = 0.f;
#pragma unroll 8
        for (int j = 0; j < 32; ++j) {
            float4 v = row[j];
            s += v.x * v.x + v.y * v.y + v.z * v.z + v.w * v.w;
        }
        g_e2[i] = s;
    }
}

// ======================================================================
// kernel 2: residual VQ — inner loop on packed f32x2 (2x FFMA throughput)
// ======================================================================
__global__ __launch_bounds__(256) void k_vq(
    const int* __restrict__ li, const float* __restrict__ lat,
    const float* __restrict__ emb)
{
    __shared__ float4 zc4[16 * 32];
    __shared__ float4 em4[64 * 33];
    __shared__ float  e2s[64];
    __shared__ int    win[16];
    __shared__ float  lred[8];

    const int t = threadIdx.x, bp = t >> 5, cl = t & 31;
    const int b0 = 2 * bp, b1 = b0 + 1;
    const int B0 = blockIdx.x * 16;
    const int l0 = li[B0 + b0], l1 = li[B0 + b1];

    float4 r0 = make_float4(0, 0, 0, 0), r1 = r0, q0 = r0, q1 = r0;
    float loss = 0.f;

    for (int s = 0; s < SSTG; ++s) {
        float4 z0 = *(const float4*)&lat[((size_t)l0 * SSTG + s) * DDIM + cl * 4];
        float4 z1 = *(const float4*)&lat[((size_t)l1 * SSTG + s) * DDIM + cl * 4];
        r0 = f4add(r0, z0); r1 = f4add(r1, z1);
        float4 ca = f4sub(r0, q0), cb = f4sub(r1, q1);
        zc4[b0 * 32 + cl] = ca;
        zc4[b1 * 32 + cl] = cb;

        float bd0 = 3.4e38f, bd1 = 3.4e38f;
        int bi0 = 0, bi1 = 0;

        for (int tb = 0; tb < KCODES; tb += 64) {
            __syncthreads();
#pragma unroll
            for (int i = 0; i < 8; ++i) {
                int lin = t + 256 * i;
                int c = lin >> 5, k4 = lin & 31;
                em4[c * 33 + k4] =
                    *(const float4*)&emb[((size_t)s * KCODES + tb + c) * DDIM + k4 * 4];
            }
            if (t < 64) e2s[t] = g_e2[s * KCODES + tb + t];
            __syncthreads();

            ull p00 = pk2(0.f, 0.f), p01 = p00, p10 = p00, p11 = p00;
#pragma unroll 4
            for (int k4 = 0; k4 < 32; ++k4) {
                float4 za = zc4[b0 * 32 + k4];
                float4 zb = zc4[b1 * 32 + k4];
                float4 e0 = em4[cl * 33 + k4];
                float4 e1 = em4[(cl + 32) * 33 + k4];
                ull zaxy = pk2(za.x, za.y), zazw = pk2(za.z, za.w);
                ull zbxy = pk2(zb.x, zb.y), zbzw = pk2(zb.z, zb.w);
                ull e0xy = pk2(e0.x, e0.y), e0zw = pk2(e0.z, e0.w);
                ull e1xy = pk2(e1.x, e1.y), e1zw = pk2(e1.z, e1.w);
                fma2(p00, zaxy, e0xy); fma2(p00, zazw, e0zw);
                fma2(p01, zbxy, e0xy); fma2(p01, zbzw, e0zw);
                fma2(p10, zaxy, e1xy); fma2(p10, zazw, e1zw);
                fma2(p11, zbxy, e1xy); fma2(p11, zbzw, e1zw);
            }
            float u, v, a00, a01, a10, a11;
            upk2(p00, u, v); a00 = u + v;
            upk2(p01, u, v); a01 = u + v;
            upk2(p10, u, v); a10 = u + v;
            upk2(p11, u, v); a11 = u + v;
            float d;
            d = fmaf(-2.f, a00, e2s[cl]);      if (d < bd0) { bd0 = d; bi0 = tb + cl; }
            d = fmaf(-2.f, a10, e2s[cl + 32]); if (d < bd0) { bd0 = d; bi0 = tb + cl + 32; }
            d = fmaf(-2.f, a01, e2s[cl]);      if (d < bd1) { bd1 = d; bi1 = tb + cl; }
            d = fmaf(-2.f, a11, e2s[cl + 32]); if (d < bd1) { bd1 = d; bi1 = tb + cl + 32; }
        }
#pragma unroll
        for (int off = 16; off; off >>= 1) {
            float od = __shfl_down_sync(~0u, bd0, off);
            int   oi = __shfl_down_sync(~0u, bi0, off);
            if (od < bd0 || (od == bd0 && oi < bi0)) { bd0 = od; bi0 = oi; }
            od = __shfl_down_sync(~0u, bd1, off);
            oi = __shfl_down_sync(~0u, bi1, off);
            if (od < bd1 || (od == bd1 && oi < bi1)) { bd1 = od; bi1 = oi; }
        }
        if (cl == 0) { win[b0] = bi0; win[b1] = bi1; }
        __syncthreads();
        int w0 = win[b0], w1 = win[b1];
        float4 e0 = *(const float4*)&emb[((size_t)s * KCODES + w0) * DDIM + cl * 4];
        float4 e1 = *(const float4*)&emb[((size_t)s * KCODES + w1) * DDIM + cl * 4];
        float4 d0 = f4sub(e0, ca), d1 = f4sub(e1, cb);
        loss += dot4(d0, d0) + dot4(d1, d1);
        q0 = f4add(q0, e0); q1 = f4add(q1, e1);
    }
    *(float4*)&g_zq[(size_t)(B0 + b0) * DDIM + cl * 4] = q0;
    *(float4*)&g_zq[(size_t)(B0 + b1) * DDIM + cl * 4] = q1;

#pragma unroll
    for (int off = 16; off; off >>= 1) loss += __shfl_down_sync(~0u, loss, off);
    if (cl == 0) lred[bp] = loss;
    __syncthreads();
    if (t == 0) {
        float s = 0.f;
        for (int i = 0; i < 8; ++i) s += lred[i];
        g_lpart[blockIdx.x] = s;
    }
}

// ======================================================================
// kernel 3: betas (validated)
// ======================================================================
__global__ __launch_bounds__(256) void k_betas(
    const float* __restrict__ mW, const float* __restrict__ mb)
{
    extern __shared__ float sm[];
    float* Zs = sm;
    float* Ws = sm + 64 * 129;
    const int t = threadIdx.x;
    const int i0 = blockIdx.x * 64, r0 = blockIdx.y * 64;
    for (int lin = t; lin < 8192; lin += 256) {
        int r = lin >> 7, k = lin & 127;
        Zs[r * 129 + k] = g_zq[(size_t)(i0 + r) * DDIM + k];
        Ws[r * 129 + k] = mW[(size_t)(r0 + r) * DDIM + k];
    }
    __syncthreads();
    const int ix = t & 15, wy = t >> 4;
    float acc[4][4] = {};
    for (int k = 0; k < 128; ++k) {
        float z[4], w[4];
#pragma unroll
        for (int m = 0; m < 4; ++m) {
            z[m] = Zs[(ix + 16 * m) * 129 + k];
            w[m] = Ws[(wy + 16 * m) * 129 + k];
        }
#pragma unroll
        for (int m = 0; m < 4; ++m)
#pragma unroll
            for (int n = 0; n < 4; ++n) acc[m][n] = fmaf(z[m], w[n], acc[m][n]);
    }
#pragma unroll
    for (int n = 0; n < 4; ++n) {
        float bias = mb[r0 + wy + 16 * n];
#pragma unroll
        for (int m = 0; m < 4; ++m)
            g_bet[(size_t)(i0 + ix + 16 * m) * LHTOT + r0 + wy + 16 * n] = acc[m][n] + bias;
    }
}

// ======================================================================
// kernel 4: fp16 HMMA fused MLP — 2 img/CTA (M=128), 512 threads, 16 warps
//   warp tile 32x64: wm = wid&3 (M 32-quarter), wn = wid>>2 (N 64-quarter)
//   acc = 64 regs/thread -> no spill at the 128-reg/thread RF cap.
//   X plane fp16 [128][264] (stride 528 B); W stages 2 x [256][72] (144 B).
//   17 K=64 double-buffered panels, 1 sync per panel.
// ======================================================================
__global__ __launch_bounds__(512, 1) void k_mlp16(
    const float* __restrict__ coords, const float* __restrict__ b0v,
    const float* __restrict__ bhv, const float* __restrict__ lW,
    const float* __restrict__ lb, float* __restrict__ out)
{
    extern __shared__ char dyn[];
    __shared__ float bbs[512];
    __shared__ float lWs[768];

    const unsigned XB = smem_u32(dyn);
    const unsigned WB = XB + 67584u;

    const int t = threadIdx.x, wid = t >> 5, l = t & 31;
    const int wm = wid & 3, wn = wid >> 2;
    const int blk = blockIdx.x;

    const unsigned aoffb = (unsigned)(wm * 32 + (l & 15)) * 528u + (unsigned)((l >> 4) << 3) * 2u;
    const unsigned boffb = (unsigned)(wn * 64 + ((l >> 4) << 3) + (l & 7)) * 144u
                         + (unsigned)(((l >> 3) & 1) << 4);

    auto issue = [&](int g) {
        const __half* Wg; int rstride, k0;
        if (g == 0) { Wg = g_W0f; rstride = 64; k0 = 0; }
        else {
            int Lw = (g - 1) >> 2;
            Wg = g_Whf + (size_t)Lw * 65536; rstride = 256; k0 = ((g - 1) & 3) * 64;
        }
        int row = t >> 1, half = t & 1;
        const __half* src = Wg + (size_t)row * rstride + k0 + half * 32;
        unsigned dst = WB + (unsigned)(g & 1) * 36864u + (unsigned)row * 144u + (unsigned)half * 64u;
#pragma unroll
        for (int c = 0; c < 4; ++c) cpa16(dst + (unsigned)c * 16u, src + c * 8);
        CPA_COMMIT();
    };

    issue(0);

    // ---- prefetch ALL bias+beta into registers (1 elem/thread/layer) ----
    const int nidx = t & 255, img = t >> 8;
    float bbr[5];
#pragma unroll
    for (int L = 0; L < 5; ++L) {
        float bias = (L == 0) ? b0v[nidx] : bhv[(L - 1) * 256 + nidx];
        bbr[L] = bias + g_bet[(size_t)(blk * 2 + img) * LHTOT + L * 256 + nidx];
    }
    for (int i = t; i < 768; i += 512) lWs[i] = lW[i];

    // ---- positional encoding -> X rows 0..127 (fp16), cols 42..63 zero ----
    if (t < 128) {
        const float* cp = coords + ((size_t)(blk * 2) * 64 + t) * 2;
        float cx = cp[0], cy = cp[1];
        unsigned rowo = XB + (unsigned)t * 528u;
        auto wrf = [&](int k, float v) {
            __half h = __float2half_rn(v);
            sts16(rowo + 2u * (unsigned)k, *(unsigned short*)&h);
        };
        wrf(0, cx); wrf(1, cy);
        float fr = 3.14159274101257324f;
#pragma unroll
        for (int f = 0; f < 10; ++f) {
            float sx, cxv, sy, cyv;
            sc_f32(cx * fr, sx, cxv);
            sc_f32(cy * fr, sy, cyv);
            wrf(2 + f, sx); wrf(12 + f, sy);
            wrf(22 + f, cxv); wrf(32 + f, cyv);
            fr *= 2.f;
        }
#pragma unroll
        for (int k = 42; k < 64; ++k) wrf(k, 0.f);
    }

    float acc[2][8][4];
#pragma unroll
    for (int mt = 0; mt < 2; ++mt)
#pragma unroll
        for (int nc = 0; nc < 8; ++nc)
#pragma unroll
            for (int q = 0; q < 4; ++q) acc[mt][nc][q] = 0.f;

    int L = 0;
#pragma unroll 1
    for (int g = 0; g < 17; ++g) {
        CPA_WAIT0();        // panel g resident
        __syncthreads();    // publishes panel g + X writes; guards stage reuse
        if (g + 1 < 17) issue(g + 1);   // overlaps mma(g)

        const unsigned wb = WB + (unsigned)(g & 1) * 36864u;
        const int kb = (g == 0) ? 0 : ((g - 1) & 3) * 64;
#pragma unroll 2
        for (int ks = 0; ks < 4; ++ks) {
            unsigned xc = (unsigned)(kb + ks * 16) * 2u;
            unsigned a[2][4];
#pragma unroll
            for (int mt = 0; mt < 2; ++mt)
                ldm4(a[mt], XB + aoffb + xc + (unsigned)mt * (16u * 528u));
#pragma unroll
            for (int bg = 0; bg < 4; ++bg) {
                unsigned bf[4];
                ldm4(bf, wb + boffb + (unsigned)bg * (16u * 144u) + (unsigned)(ks * 32));
#pragma unroll
                for (int mt = 0; mt < 2; ++mt) {
                    mma_f16h(acc[mt][2 * bg],     a[mt], bf[0], bf[1]);
                    mma_f16h(acc[mt][2 * bg + 1], a[mt], bf[2], bf[3]);
                }
            }
        }

        const bool layerEnd = (g == 0) || ((g - 1) & 3) == 3;
        if (layerEnd) {
            __syncthreads();          // all warps done reading X this layer
            bbs[t] = bbr[L];
            __syncthreads();
            const float* bb = bbs + (wm >> 1) * 256;   // image = row>>6 = wm>>1
#pragma unroll
            for (int mt = 0; mt < 2; ++mt) {
                unsigned ro0 = XB + (unsigned)(wm * 32 + mt * 16 + (l >> 2)) * 528u;
                unsigned ro1 = ro0 + 8u * 528u;
#pragma unroll
                for (int nc = 0; nc < 8; ++nc) {
                    int cb = wn * 64 + nc * 8 + (l & 3) * 2;
                    float b0f = bb[cb], b1f = bb[cb + 1];
                    float x0 = fmaxf(acc[mt][nc][0] + b0f, 0.f);
                    float x1 = fmaxf(acc[mt][nc][1] + b1f, 0.f);
                    float y0 = fmaxf(acc[mt][nc][2] + b0f, 0.f);
                    float y1 = fmaxf(acc[mt][nc][3] + b1f, 0.f);
                    __half2 h0 = __floats2half2_rn(x0, x1);
                    __half2 h1 = __floats2half2_rn(y0, y1);
                    sts32(ro0 + (unsigned)cb * 2u, *(unsigned*)&h0);
                    sts32(ro1 + (unsigned)cb * 2u, *(unsigned*)&h1);
                    acc[mt][nc][0] = 0.f; acc[mt][nc][1] = 0.f;
                    acc[mt][nc][2] = 0.f; acc[mt][nc][3] = 0.f;
                }
            }
            ++L;
            // next panel's top __syncthreads publishes the new X
        }
    }
    __syncthreads();   // final X visible

    // ---- final linear layer: V=3, fp32 from fp16 plane ----
    if (t < 128) {
        float a0 = 0.f, a1 = 0.f, a2 = 0.f;
        unsigned xr = XB + (unsigned)t * 528u;
#pragma unroll 8
        for (int k2 = 0; k2 < 128; ++k2) {
            unsigned hv = lds32(xr + k2 * 4u);
            __half2 h = *(__half2*)&hv;
            float x0 = __half2float(h.x), x1 = __half2float(h.y);
            int k = 2 * k2;
            a0 = fmaf(x0, lWs[k], fmaf(x1, lWs[k + 1], a0));
            a1 = fmaf(x0, lWs[256 + k], fmaf(x1, lWs[256 + k + 1], a1));
            a2 = fmaf(x0, lWs[512 + k], fmaf(x1, lWs[512 + k + 1], a2));
        }
        size_t ob = ((size_t)blk * 128 + t) * 3;
        out[ob]     = a0 + lb[0];
        out[ob + 1] = a1 + lb[1];
        out[ob + 2] = a2 + lb[2];
    }
}

// ======================================================================
// kernel 5: deterministic loss finalize
// ======================================================================
__global__ void k_loss(float* out, int has) {
    if (!has) return;
    float s = 0.f;
    for (int i = 0; i < 256; ++i) s += g_lpart[i];
    out[786432] = s * (0.25f / (4096.f * 128.f));
}

extern "C" void kernel_launch(void* const* d_in, const int* in_sizes, int n_in,
                              void* d_out, int out_size) {
    const float* coords = (const float*)d_in[0];
    const int*   li     = (const int*)d_in[1];
    const float* lat    = (const float*)d_in[2];
    const float* emb    = (const float*)d_in[3];
    const float* mW     = (const float*)d_in[4];
    const float* mb     = (const float*)d_in[5];
    const float* W0     = (const float*)d_in[6];
    const float* b0v    = (const float*)d_in[7];
    const float* Wh     = (const float*)d_in[8];
    const float* bh     = (const float*)d_in[9];
    const float* lW     = (const float*)d_in[10];
    const float* lb     = (const float*)d_in[11];
    float* out = (float*)d_out;

    const int MLP_SMEM = 141312;   // X fp16 (67584) + 2 W stages (2*36864)
    cudaFuncSetAttribute(k_mlp16, cudaFuncAttributeMaxDynamicSharedMemorySize, MLP_SMEM);
    cudaFuncSetAttribute(k_betas, cudaFuncAttributeMaxDynamicSharedMemorySize, 66048);

    k_prep<<<1024, 256>>>(W0, Wh, emb);
    k_vq<<<256, 256>>>(li, lat, emb);
    k_betas<<<dim3(64, 20), 256, 66048>>>(mW, mb);
    k_mlp16<<<2048, 512, MLP_SMEM>>>(coords, b0v, bh, lW, lb, out);
    k_loss<<<1, 1>>>(out, out_size > 786432 ? 1 : 0);
}

// round 13
// speedup vs baseline: 1.6392x; 1.1402x over previous
#include <cuda_runtime.h>
#include <cuda_bf16.h>
#include <cuda_fp16.h>
#include <math.h>

#define BSZ 4096
#define DDIM 128
#define KCODES 2048
#define SSTG 4
#define LHTOT 1280

// -------- device scratch (static; no allocation) --------
__device__ float g_zq[BSZ * DDIM];
__device__ float g_bet[BSZ * LHTOT];
__device__ float g_e2[SSTG * KCODES];
__device__ float g_lpart[128];
__device__ __half g_W0f[256 * 64];
__device__ __half g_Whf[4 * 256 * 256];

typedef unsigned long long ull;

// -------- generic helpers --------
__device__ __forceinline__ float dot4(float4 a, float4 b) {
    return fmaf(a.x, b.x, fmaf(a.y, b.y, fmaf(a.z, b.z, a.w * b.w)));
}
__device__ __forceinline__ float4 f4add(float4 a, float4 b) {
    return make_float4(a.x + b.x, a.y + b.y, a.z + b.z, a.w + b.w);
}
__device__ __forceinline__ float4 f4sub(float4 a, float4 b) {
    return make_float4(a.x - b.x, a.y - b.y, a.z - b.z, a.w - b.w);
}
__device__ __forceinline__ unsigned smem_u32(const void* p) {
    unsigned a;
    asm("{ .reg .u64 t; cvta.to.shared.u64 t, %1; cvt.u32.u64 %0, t; }" : "=r"(a) : "l"(p));
    return a;
}
__device__ __forceinline__ void sts32(unsigned a, unsigned v) {
    asm volatile("st.shared.u32 [%0], %1;" :: "r"(a), "r"(v));
}
__device__ __forceinline__ void sts16(unsigned a, unsigned short v) {
    asm volatile("st.shared.u16 [%0], %1;" :: "r"(a), "h"(v));
}
__device__ __forceinline__ unsigned lds32(unsigned a) {
    unsigned v; asm volatile("ld.shared.b32 %0, [%1];" : "=r"(v) : "r"(a)); return v;
}
__device__ __forceinline__ void ldm4(unsigned* r, unsigned a) {
    asm volatile("ldmatrix.sync.aligned.m8n8.x4.shared.b16 {%0,%1,%2,%3}, [%4];"
        : "=r"(r[0]), "=r"(r[1]), "=r"(r[2]), "=r"(r[3]) : "r"(a));
}
// fp16 mma m16n8k16 -> f32 accum (baseline sm_80)
__device__ __forceinline__ void mma_f16h(float* c, const unsigned* a, unsigned b0, unsigned b1) {
    asm volatile("mma.sync.aligned.m16n8k16.row.col.f32.f16.f16.f32 "
        "{%0,%1,%2,%3},{%4,%5,%6,%7},{%8,%9},{%0,%1,%2,%3};"
        : "+f"(c[0]), "+f"(c[1]), "+f"(c[2]), "+f"(c[3])
        : "r"(a[0]), "r"(a[1]), "r"(a[2]), "r"(a[3]), "r"(b0), "r"(b1));
}
__device__ __forceinline__ void cpa16(unsigned dst, const void* src) {
    asm volatile("cp.async.cg.shared.global [%0], [%1], 16;" :: "r"(dst), "l"(src));
}
#define CPA_COMMIT() asm volatile("cp.async.commit_group;" ::: "memory")
#define CPA_WAIT0()  asm volatile("cp.async.wait_group 0;" ::: "memory")

// packed fp32x2
__device__ __forceinline__ void upk2(ull v, float& x, float& y) {
    asm("mov.b64 {%0,%1},%2;" : "=f"(x), "=f"(y) : "l"(v));
}
__device__ __forceinline__ void fma2(ull& d, ull a, ull b) {
    asm("fma.rn.f32x2 %0,%1,%2,%0;" : "+l"(d) : "l"(a), "l"(b));
}

// accurate fp32 sincos (Cody-Waite; |a| <= 2^9*pi)
__device__ __forceinline__ void sc_f32(float a, float& s, float& c) {
    float n = rintf(a * 0.31830988618f);
    float r = fmaf(-n, 3.140625f, a);
    r = fmaf(-n, 9.67502593994140625e-4f, r);
    r = fmaf(-n, 1.50995788e-7f, r);
    float r2 = r * r;
    float sp = fmaf(r2, fmaf(r2, fmaf(r2, fmaf(r2, fmaf(r2, -2.5052108e-8f, 2.7557319e-6f),
               -1.9841270e-4f), 8.3333333e-3f), -1.6666667e-1f), 1.f);
    float cp = fmaf(r2, fmaf(r2, fmaf(r2, fmaf(r2, fmaf(r2, -2.7557319e-7f, 2.4801587e-5f),
               -1.3888889e-3f), 4.1666667e-2f), -0.5f), 1.f);
    s = r * sp; c = cp;
    if (((int)n) & 1) { s = -s; c = -c; }
}

// ======================================================================
// kernel 1: fused prep — fp16 weight conversion + ||e||^2
// ======================================================================
__global__ void k_prep(const float* __restrict__ W0, const float* __restrict__ Wh,
                       const float* __restrict__ emb) {
    int i = blockIdx.x * 256 + threadIdx.x;   // 0 .. 262143
    if (i < 256 * 64) {
        int n = i >> 6, k = i & 63;
        float w = (k < 42) ? W0[n * 42 + k] : 0.f;
        g_W0f[i] = __float2half_rn(w);
    }
    g_Whf[i] = __float2half_rn(Wh[i]);
    if (i < SSTG * KCODES) {
        const float4* row = (const float4*)(emb + (size_t)i * DDIM);
        float s = 0.f;
#pragma unroll 8
        for (int j = 0; j < 32; ++j) {
            float4 v = row[j];
            s += v.x * v.x + v.y * v.y + v.z * v.z + v.w * v.w;
        }
        g_e2[i] = s;
    }
}

// ======================================================================
// kernel 2: residual VQ — 32 images/CTA, 4 images/warp (4x codebook reuse)
//   128 CTAs x 256 thr (single wave). Lane cl scores codes cl & cl+32 of
//   each 64-code tile vs 4 images; z broadcast from smem, e loaded as
//   ulonglong2 -> free f32x2 packing. Winners broadcast via shfl (zc rows
//   are warp-private; no smem / extra syncs needed).
// ======================================================================
__global__ __launch_bounds__(256) void k_vq(
    const int* __restrict__ li, const float* __restrict__ lat,
    const float* __restrict__ emb)
{
    extern __shared__ char vsm[];
    ulonglong2* zc4 = (ulonglong2*)vsm;                     // [32 img][32 k4]  16384 B
    ulonglong2* em4 = (ulonglong2*)(vsm + 16384);           // [64 code][33]    33792 B
    float* e2s = (float*)(vsm + 16384 + 33792);             // 64
    float* lred = e2s + 64;                                 // 8

    const int t = threadIdx.x, bp = t >> 5, cl = t & 31;
    const int B0 = blockIdx.x * 32;
    int lidx[4];
#pragma unroll
    for (int i = 0; i < 4; ++i) lidx[i] = li[B0 + 4 * bp + i];

    float4 r[4], q[4];
#pragma unroll
    for (int i = 0; i < 4; ++i) { r[i] = make_float4(0, 0, 0, 0); q[i] = r[i]; }
    float loss = 0.f;

    for (int s = 0; s < SSTG; ++s) {
        float4 c[4];
#pragma unroll
        for (int i = 0; i < 4; ++i) {
            float4 z = *(const float4*)&lat[((size_t)lidx[i] * SSTG + s) * DDIM + cl * 4];
            r[i] = f4add(r[i], z);
            c[i] = f4sub(r[i], q[i]);
            zc4[(4 * bp + i) * 32 + cl] = *(ulonglong2*)&c[i];   // warp-private rows
        }

        float bd[4]; int bi[4];
#pragma unroll
        for (int i = 0; i < 4; ++i) { bd[i] = 3.4e38f; bi[i] = 0; }

        for (int tb = 0; tb < KCODES; tb += 64) {
            __syncthreads();   // em4 reuse guard (also publishes zc4 on first tile)
#pragma unroll
            for (int j = 0; j < 8; ++j) {
                int lin = t + 256 * j;
                int cc = lin >> 5, k4 = lin & 31;
                em4[cc * 33 + k4] =
                    *(const ulonglong2*)&emb[((size_t)s * KCODES + tb + cc) * DDIM + k4 * 4];
            }
            if (t < 64) e2s[t] = g_e2[s * KCODES + tb + t];
            __syncthreads();

            ull p[4][2];
#pragma unroll
            for (int i = 0; i < 4; ++i) { p[i][0] = 0ull; p[i][1] = 0ull; }
#pragma unroll 4
            for (int k4 = 0; k4 < 32; ++k4) {
                ulonglong2 e0 = em4[cl * 33 + k4];
                ulonglong2 e1 = em4[(cl + 32) * 33 + k4];
#pragma unroll
                for (int i = 0; i < 4; ++i) {
                    ulonglong2 z = zc4[(4 * bp + i) * 32 + k4];   // broadcast
                    fma2(p[i][0], z.x, e0.x); fma2(p[i][0], z.y, e0.y);
                    fma2(p[i][1], z.x, e1.x); fma2(p[i][1], z.y, e1.y);
                }
            }
            float e2a = e2s[cl], e2b = e2s[cl + 32];
#pragma unroll
            for (int i = 0; i < 4; ++i) {
                float u, v;
                upk2(p[i][0], u, v); float d0 = fmaf(-2.f, u + v, e2a);
                upk2(p[i][1], u, v); float d1 = fmaf(-2.f, u + v, e2b);
                if (d0 < bd[i]) { bd[i] = d0; bi[i] = tb + cl; }
                if (d1 < bd[i]) { bd[i] = d1; bi[i] = tb + cl + 32; }
            }
        }

        // warp lexicographic argmin per image, then shfl-broadcast winner
#pragma unroll
        for (int i = 0; i < 4; ++i) {
#pragma unroll
            for (int off = 16; off; off >>= 1) {
                float od = __shfl_down_sync(~0u, bd[i], off);
                int   oi = __shfl_down_sync(~0u, bi[i], off);
                if (od < bd[i] || (od == bd[i] && oi < bi[i])) { bd[i] = od; bi[i] = oi; }
            }
            int w = __shfl_sync(~0u, bi[i], 0);
            float4 e = *(const float4*)&emb[((size_t)s * KCODES + w) * DDIM + cl * 4];
            float4 dd = f4sub(e, c[i]);
            loss += dot4(dd, dd);
            q[i] = f4add(q[i], e);
        }
    }
#pragma unroll
    for (int i = 0; i < 4; ++i)
        *(float4*)&g_zq[(size_t)(B0 + 4 * bp + i) * DDIM + cl * 4] = q[i];

#pragma unroll
    for (int off = 16; off; off >>= 1) loss += __shfl_down_sync(~0u, loss, off);
    if (cl == 0) lred[bp] = loss;
    __syncthreads();
    if (t == 0) {
        float s = 0.f;
        for (int i = 0; i < 8; ++i) s += lred[i];
        g_lpart[blockIdx.x] = s;
    }
}

// ======================================================================
// kernel 3: betas (validated)
// ======================================================================
__global__ __launch_bounds__(256) void k_betas(
    const float* __restrict__ mW, const float* __restrict__ mb)
{
    extern __shared__ float sm[];
    float* Zs = sm;
    float* Ws = sm + 64 * 129;
    const int t = threadIdx.x;
    const int i0 = blockIdx.x * 64, r0 = blockIdx.y * 64;
    for (int lin = t; lin < 8192; lin += 256) {
        int r = lin >> 7, k = lin & 127;
        Zs[r * 129 + k] = g_zq[(size_t)(i0 + r) * DDIM + k];
        Ws[r * 129 + k] = mW[(size_t)(r0 + r) * DDIM + k];
    }
    __syncthreads();
    const int ix = t & 15, wy = t >> 4;
    float acc[4][4] = {};
    for (int k = 0; k < 128; ++k) {
        float z[4], w[4];
#pragma unroll
        for (int m = 0; m < 4; ++m) {
            z[m] = Zs[(ix + 16 * m) * 129 + k];
            w[m] = Ws[(wy + 16 * m) * 129 + k];
        }
#pragma unroll
        for (int m = 0; m < 4; ++m)
#pragma unroll
            for (int n = 0; n < 4; ++n) acc[m][n] = fmaf(z[m], w[n], acc[m][n]);
    }
#pragma unroll
    for (int n = 0; n < 4; ++n) {
        float bias = mb[r0 + wy + 16 * n];
#pragma unroll
        for (int m = 0; m < 4; ++m)
            g_bet[(size_t)(i0 + ix + 16 * m) * LHTOT + r0 + wy + 16 * n] = acc[m][n] + bias;
    }
}

// ======================================================================
// kernel 4: fp16 HMMA fused MLP — unchanged from R12 best (603 us)
// ======================================================================
__global__ __launch_bounds__(512, 1) void k_mlp16(
    const float* __restrict__ coords, const float* __restrict__ b0v,
    const float* __restrict__ bhv, const float* __restrict__ lW,
    const float* __restrict__ lb, float* __restrict__ out)
{
    extern __shared__ char dyn[];
    __shared__ float bbs[512];
    __shared__ float lWs[768];

    const unsigned XB = smem_u32(dyn);
    const unsigned WB = XB + 67584u;

    const int t = threadIdx.x, wid = t >> 5, l = t & 31;
    const int wm = wid & 3, wn = wid >> 2;
    const int blk = blockIdx.x;

    const unsigned aoffb = (unsigned)(wm * 32 + (l & 15)) * 528u + (unsigned)((l >> 4) << 3) * 2u;
    const unsigned boffb = (unsigned)(wn * 64 + ((l >> 4) << 3) + (l & 7)) * 144u
                         + (unsigned)(((l >> 3) & 1) << 4);

    auto issue = [&](int g) {
        const __half* Wg; int rstride, k0;
        if (g == 0) { Wg = g_W0f; rstride = 64; k0 = 0; }
        else {
            int Lw = (g - 1) >> 2;
            Wg = g_Whf + (size_t)Lw * 65536; rstride = 256; k0 = ((g - 1) & 3) * 64;
        }
        int row = t >> 1, half = t & 1;
        const __half* src = Wg + (size_t)row * rstride + k0 + half * 32;
        unsigned dst = WB + (unsigned)(g & 1) * 36864u + (unsigned)row * 144u + (unsigned)half * 64u;
#pragma unroll
        for (int c = 0; c < 4; ++c) cpa16(dst + (unsigned)c * 16u, src + c * 8);
        CPA_COMMIT();
    };

    issue(0);

    const int nidx = t & 255, img = t >> 8;
    float bbr[5];
#pragma unroll
    for (int L = 0; L < 5; ++L) {
        float bias = (L == 0) ? b0v[nidx] : bhv[(L - 1) * 256 + nidx];
        bbr[L] = bias + g_bet[(size_t)(blk * 2 + img) * LHTOT + L * 256 + nidx];
    }
    for (int i = t; i < 768; i += 512) lWs[i] = lW[i];

    if (t < 128) {
        const float* cp = coords + ((size_t)(blk * 2) * 64 + t) * 2;
        float cx = cp[0], cy = cp[1];
        unsigned rowo = XB + (unsigned)t * 528u;
        auto wrf = [&](int k, float v) {
            __half h = __float2half_rn(v);
            sts16(rowo + 2u * (unsigned)k, *(unsigned short*)&h);
        };
        wrf(0, cx); wrf(1, cy);
        float fr = 3.14159274101257324f;
#pragma unroll
        for (int f = 0; f < 10; ++f) {
            float sx, cxv, sy, cyv;
            sc_f32(cx * fr, sx, cxv);
            sc_f32(cy * fr, sy, cyv);
            wrf(2 + f, sx); wrf(12 + f, sy);
            wrf(22 + f, cxv); wrf(32 + f, cyv);
            fr *= 2.f;
        }
#pragma unroll
        for (int k = 42; k < 64; ++k) wrf(k, 0.f);
    }

    float acc[2][8][4];
#pragma unroll
    for (int mt = 0; mt < 2; ++mt)
#pragma unroll
        for (int nc = 0; nc < 8; ++nc)
#pragma unroll
            for (int q = 0; q < 4; ++q) acc[mt][nc][q] = 0.f;

    int L = 0;
#pragma unroll 1
    for (int g = 0; g < 17; ++g) {
        CPA_WAIT0();
        __syncthreads();
        if (g + 1 < 17) issue(g + 1);

        const unsigned wb = WB + (unsigned)(g & 1) * 36864u;
        const int kb = (g == 0) ? 0 : ((g - 1) & 3) * 64;
#pragma unroll 2
        for (int ks = 0; ks < 4; ++ks) {
            unsigned xc = (unsigned)(kb + ks * 16) * 2u;
            unsigned a[2][4];
#pragma unroll
            for (int mt = 0; mt < 2; ++mt)
                ldm4(a[mt], XB + aoffb + xc + (unsigned)mt * (16u * 528u));
#pragma unroll
            for (int bg = 0; bg < 4; ++bg) {
                unsigned bf[4];
                ldm4(bf, wb + boffb + (unsigned)bg * (16u * 144u) + (unsigned)(ks * 32));
#pragma unroll
                for (int mt = 0; mt < 2; ++mt) {
                    mma_f16h(acc[mt][2 * bg],     a[mt], bf[0], bf[1]);
                    mma_f16h(acc[mt][2 * bg + 1], a[mt], bf[2], bf[3]);
                }
            }
        }

        const bool layerEnd = (g == 0) || ((g - 1) & 3) == 3;
        if (layerEnd) {
            __syncthreads();
            bbs[t] = bbr[L];
            __syncthreads();
            const float* bb = bbs + (wm >> 1) * 256;
#pragma unroll
            for (int mt = 0; mt < 2; ++mt) {
                unsigned ro0 = XB + (unsigned)(wm * 32 + mt * 16 + (l >> 2)) * 528u;
                unsigned ro1 = ro0 + 8u * 528u;
#pragma unroll
                for (int nc = 0; nc < 8; ++nc) {
                    int cb = wn * 64 + nc * 8 + (l & 3) * 2;
                    float b0f = bb[cb], b1f = bb[cb + 1];
                    float x0 = fmaxf(acc[mt][nc][0] + b0f, 0.f);
                    float x1 = fmaxf(acc[mt][nc][1] + b1f, 0.f);
                    float y0 = fmaxf(acc[mt][nc][2] + b0f, 0.f);
                    float y1 = fmaxf(acc[mt][nc][3] + b1f, 0.f);
                    __half2 h0 = __floats2half2_rn(x0, x1);
                    __half2 h1 = __floats2half2_rn(y0, y1);
                    sts32(ro0 + (unsigned)cb * 2u, *(unsigned*)&h0);
                    sts32(ro1 + (unsigned)cb * 2u, *(unsigned*)&h1);
                    acc[mt][nc][0] = 0.f; acc[mt][nc][1] = 0.f;
                    acc[mt][nc][2] = 0.f; acc[mt][nc][3] = 0.f;
                }
            }
            ++L;
        }
    }
    __syncthreads();

    if (t < 128) {
        float a0 = 0.f, a1 = 0.f, a2 = 0.f;
        unsigned xr = XB + (unsigned)t * 528u;
#pragma unroll 8
        for (int k2 = 0; k2 < 128; ++k2) {
            unsigned hv = lds32(xr + k2 * 4u);
            __half2 h = *(__half2*)&hv;
            float x0 = __half2float(h.x), x1 = __half2float(h.y);
            int k = 2 * k2;
            a0 = fmaf(x0, lWs[k], fmaf(x1, lWs[k + 1], a0));
            a1 = fmaf(x0, lWs[256 + k], fmaf(x1, lWs[256 + k + 1], a1));
            a2 = fmaf(x0, lWs[512 + k], fmaf(x1, lWs[512 + k + 1], a2));
        }
        size_t ob = ((size_t)blk * 128 + t) * 3;
        out[ob]     = a0 + lb[0];
        out[ob + 1] = a1 + lb[1];
        out[ob + 2] = a2 + lb[2];
    }
}

// ======================================================================
// kernel 5: deterministic loss finalize
// ======================================================================
__global__ void k_loss(float* out, int has) {
    if (!has) return;
    float s = 0.f;
    for (int i = 0; i < 128; ++i) s += g_lpart[i];
    out[786432] = s * (0.25f / (4096.f * 128.f));
}

extern "C" void kernel_launch(void* const* d_in, const int* in_sizes, int n_in,
                              void* d_out, int out_size) {
    const float* coords = (const float*)d_in[0];
    const int*   li     = (const int*)d_in[1];
    const float* lat    = (const float*)d_in[2];
    const float* emb    = (const float*)d_in[3];
    const float* mW     = (const float*)d_in[4];
    const float* mb     = (const float*)d_in[5];
    const float* W0     = (const float*)d_in[6];
    const float* b0v    = (const float*)d_in[7];
    const float* Wh     = (const float*)d_in[8];
    const float* bh     = (const float*)d_in[9];
    const float* lW     = (const float*)d_in[10];
    const float* lb     = (const float*)d_in[11];
    float* out = (float*)d_out;

    const int MLP_SMEM = 141312;   // X fp16 (67584) + 2 W stages (2*36864)
    const int VQ_SMEM  = 50560;    // zc4 16384 + em4 33792 + e2s/lred
    cudaFuncSetAttribute(k_mlp16, cudaFuncAttributeMaxDynamicSharedMemorySize, MLP_SMEM);
    cudaFuncSetAttribute(k_vq,    cudaFuncAttributeMaxDynamicSharedMemorySize, VQ_SMEM);
    cudaFuncSetAttribute(k_betas, cudaFuncAttributeMaxDynamicSharedMemorySize, 66048);

    k_prep<<<1024, 256>>>(W0, Wh, emb);
    k_vq<<<128, 256, VQ_SMEM>>>(li, lat, emb);
    k_betas<<<dim3(64, 20), 256, 66048>>>(mW, mb);
    k_mlp16<<<2048, 512, MLP_SMEM>>>(coords, b0v, bh, lW, lb, out);
    k_loss<<<1, 1>>>(out, out_size > 786432 ? 1 : 0);
}